// round 3
// baseline (speedup 1.0000x reference)
#include <cuda_runtime.h>
#include <cstdint>

// QConv2d split into two balanced kernels via a device-global scratch.
//   new_rho[(c,P),(c',P')] = sum_{e,e'} cc[c,e] cc[c',e'] A[(e,P),(e',P')]
//   cc[c,e] = uc[c,e+2],  A = L rho L^T,  L = I2 (x) ux (x) uy (separable).
// K1: scratch = L rho          (column-parallel, grid 1024)
// K2: out = expand(scratch L^T) (row-parallel,   grid 1024)

typedef unsigned long long u64;

__device__ float g_scratch[256 * 128 * 128];   // 16 MB intermediate

__device__ __forceinline__ u64 pk2(float a, float b) {
    u64 r; asm("mov.b64 %0,{%1,%2};" : "=l"(r) : "f"(a), "f"(b)); return r;
}
__device__ __forceinline__ u64 mul2(u64 a, u64 b) {
    u64 r; asm("mul.rn.f32x2 %0,%1,%2;" : "=l"(r) : "l"(a), "l"(b)); return r;
}
__device__ __forceinline__ void fma2(u64& d, u64 a, u64 b) {
    asm("fma.rn.f32x2 %0,%1,%2,%0;" : "+l"(d) : "l"(a), "l"(b));
}

// ======================= K1: left transform =======================
// CTA = (b, cb): 32-column block. LDG -> uy pass -> smem -> ux pass -> STG.
#define ST1 36   // 32 + 4 pad, keeps 16B row alignment, conflict-free

__global__ __launch_bounds__(128, 8)
void qconv2d_k1(const float* __restrict__ rho,
                const float* __restrict__ ux,
                const float* __restrict__ uy) {
    __shared__ float A[128 * ST1];
    __shared__ u64 uxd[64], uyd[64];

    const int t  = threadIdx.x;
    const int b  = blockIdx.x >> 2;
    const int cb = blockIdx.x & 3;

    if (t < 64) { float vx = ux[t], vy = uy[t]; uxd[t] = pk2(vx, vx); uyd[t] = pk2(vy, vy); }

    const int cq = t & 7;        // column quad within 32-col block
    const int gi = t >> 3;       // (e,i) group 0..15

    // Pass A: contract uy over j (rows gi*8+j), straight from GMEM.
    const float* rb = rho + (size_t)b * 16384 + cb * 32 + 4 * cq;
    ulonglong2 in[8];
#pragma unroll
    for (int j = 0; j < 8; j++)
        in[j] = *(const ulonglong2*)(rb + (size_t)(gi * 8 + j) * 128);
    __syncthreads();             // tables ready
#pragma unroll
    for (int k = 0; k < 8; k++) {
        u64 c0 = uyd[k * 8];
        u64 ax = mul2(c0, in[0].x), ay = mul2(c0, in[0].y);
#pragma unroll
        for (int j = 1; j < 8; j++) { u64 c = uyd[k * 8 + j]; fma2(ax, c, in[j].x); fma2(ay, c, in[j].y); }
        ulonglong2 o; o.x = ax; o.y = ay;
        *(ulonglong2*)&A[(gi * 8 + k) * ST1 + 4 * cq] = o;
    }
    __syncthreads();

    // Pass B: contract ux over i (rows e*64+i*8+kj), write scratch.
    const int kj = (t >> 3) & 7;
    const int e  = t >> 6;
    float* sb = g_scratch + (size_t)b * 16384 + cb * 32 + 4 * cq;
    ulonglong2 in2[8];
#pragma unroll
    for (int i = 0; i < 8; i++)
        in2[i] = *(ulonglong2*)&A[(e * 64 + i * 8 + kj) * ST1 + 4 * cq];
#pragma unroll
    for (int k = 0; k < 8; k++) {
        u64 c0 = uxd[k * 8];
        u64 ax = mul2(c0, in2[0].x), ay = mul2(c0, in2[0].y);
#pragma unroll
        for (int i = 1; i < 8; i++) { u64 c = uxd[k * 8 + i]; fma2(ax, c, in2[i].x); fma2(ay, c, in2[i].y); }
        ulonglong2 o; o.x = ax; o.y = ay;
        *(ulonglong2*)(sb + (size_t)(e * 64 + k * 8 + kj) * 128) = o;
    }
}

// ======================= K2: right transform + channel expansion =======================
// CTA = (b, pb): 16 pixel rows P0..P0+15 for BOTH e -> 32 local rows.
#define ST2 132

__global__ __launch_bounds__(128, 8)
void qconv2d_k2(const float* __restrict__ ux,
                const float* __restrict__ uy,
                const float* __restrict__ uc,
                float* __restrict__ out) {
    __shared__ float A[32 * ST2];
    __shared__ u64 uxd[64], uypp[32], sccd[8];

    const int t  = threadIdx.x;
    const int b  = blockIdx.x >> 2;
    const int P0 = (blockIdx.x & 3) * 16;

    if (t < 64) { float vx = ux[t]; uxd[t] = pk2(vx, vx); }
    else if (t < 96) {
        int m = t - 64, kp = m >> 3, j = m & 7;
        uypp[m] = pk2(uy[(2 * kp) * 8 + j], uy[(2 * kp + 1) * 8 + j]);
    } else if (t < 104) {
        int m = t - 96; float v = uc[(m >> 1) * 4 + 2 + (m & 1)];
        sccd[m] = pk2(v, v);
    }
    __syncthreads();

    // Pass C: contract uy over j' (columns), LDG from scratch -> smem.
    const float* sb = g_scratch + (size_t)b * 16384;
#pragma unroll 1
    for (int it = 0; it < 4; it++) {
        int task = t + 128 * it;
        int r = task & 31, cg = task >> 5;           // cg = (e',i') 0..15
        int p = r & 15, half = r >> 4;               // local row r = half*16+p
        const float* row = sb + (size_t)(half * 64 + P0 + p) * 128 + cg * 8;
        float4 pv = *(const float4*)row;
        float4 qv = *(const float4*)(row + 4);
        u64 d0 = pk2(pv.x, pv.x), d1 = pk2(pv.y, pv.y), d2 = pk2(pv.z, pv.z), d3 = pk2(pv.w, pv.w);
        u64 d4 = pk2(qv.x, qv.x), d5 = pk2(qv.y, qv.y), d6 = pk2(qv.z, qv.z), d7 = pk2(qv.w, qv.w);
        u64 o[4];
#pragma unroll
        for (int kp = 0; kp < 4; kp++) {
            u64 acc = mul2(uypp[kp * 8 + 0], d0);
            fma2(acc, uypp[kp * 8 + 1], d1); fma2(acc, uypp[kp * 8 + 2], d2);
            fma2(acc, uypp[kp * 8 + 3], d3); fma2(acc, uypp[kp * 8 + 4], d4);
            fma2(acc, uypp[kp * 8 + 5], d5); fma2(acc, uypp[kp * 8 + 6], d6);
            fma2(acc, uypp[kp * 8 + 7], d7);
            o[kp] = acc;
        }
        ulonglong2 w0, w1; w0.x = o[0]; w0.y = o[1]; w1.x = o[2]; w1.y = o[3];
        *(ulonglong2*)&A[r * ST2 + cg * 8] = w0;
        *(ulonglong2*)&A[r * ST2 + cg * 8 + 4] = w1;
    }
    __syncthreads();

    // Pass D: contract ux over i' (columns e2*64 + i*8 + kj quad), in place.
    {
        int r = t & 31, e2 = (t >> 5) & 1, kjq = t >> 6;
        int base = r * ST2 + e2 * 64 + 4 * kjq;
        ulonglong2 in[8];
#pragma unroll
        for (int i = 0; i < 8; i++) in[i] = *(ulonglong2*)&A[base + 8 * i];
#pragma unroll
        for (int k = 0; k < 8; k++) {
            u64 c0 = uxd[k * 8];
            u64 ax = mul2(c0, in[0].x), ay = mul2(c0, in[0].y);
#pragma unroll
            for (int i = 1; i < 8; i++) { u64 c = uxd[k * 8 + i]; fma2(ax, c, in[i].x); fma2(ay, c, in[i].y); }
            ulonglong2 o; o.x = ax; o.y = ay;
            *(ulonglong2*)&A[base + 8 * k] = o;
        }
    }
    __syncthreads();

    // Epilogue: channel expansion, one read of each A quadrant, STG.128.
#pragma unroll 1
    for (int it = 0; it < 2; it++) {
        int task = t + 128 * it;
        int q = task & 15, p = task >> 4;            // col quad, pixel row
        ulonglong2 a00 = *(ulonglong2*)&A[p * ST2 + 4 * q];
        ulonglong2 a01 = *(ulonglong2*)&A[p * ST2 + 64 + 4 * q];
        ulonglong2 a10 = *(ulonglong2*)&A[(16 + p) * ST2 + 4 * q];
        ulonglong2 a11 = *(ulonglong2*)&A[(16 + p) * ST2 + 64 + 4 * q];
        float* ob = out + (size_t)b * 65536 + (size_t)(P0 + p) * 256 + 4 * q;
#pragma unroll
        for (int cp = 0; cp < 4; cp++) {
            u64 k0 = sccd[2 * cp], k1 = sccd[2 * cp + 1];
            u64 v0x = mul2(k0, a00.x); fma2(v0x, k1, a01.x);
            u64 v0y = mul2(k0, a00.y); fma2(v0y, k1, a01.y);
            u64 v1x = mul2(k0, a10.x); fma2(v1x, k1, a11.x);
            u64 v1y = mul2(k0, a10.y); fma2(v1y, k1, a11.y);
#pragma unroll
            for (int c = 0; c < 4; c++) {
                u64 ox = mul2(sccd[2 * c], v0x); fma2(ox, sccd[2 * c + 1], v1x);
                u64 oy = mul2(sccd[2 * c], v0y); fma2(oy, sccd[2 * c + 1], v1y);
                ulonglong2 w; w.x = ox; w.y = oy;
                *(ulonglong2*)(ob + (size_t)(c * 64) * 256 + cp * 64) = w;
            }
        }
    }
}

extern "C" void kernel_launch(void* const* d_in, const int* in_sizes, int n_in,
                              void* d_out, int out_size) {
    const float* rho = (const float*)d_in[0];   // [256,128,128]
    const float* ux  = (const float*)d_in[1];   // [8,8]
    const float* uy  = (const float*)d_in[2];   // [8,8]
    const float* uc  = (const float*)d_in[3];   // [4,4]
    float* out = (float*)d_out;                 // [256,256,256]

    qconv2d_k1<<<1024, 128>>>(rho, ux, uy);
    qconv2d_k2<<<1024, 128>>>(ux, uy, uc, out);
}

// round 4
// speedup vs baseline: 1.2929x; 1.2929x over previous
#include <cuda_runtime.h>
#include <cstdint>

// QConv2d fused single kernel: new_rho = U rho_big U^T, U = kron(uc, ux (x) uy).
// rho_big[:,128:,128:] = rho  =>  new_rho[(c,P),(c',P')] =
//   sum_{e,e'} cc[c,e] cc[c',e'] A[(e,P),(e',P')],  cc[c,e]=uc[c,e+2],
//   A = (I2 (x) ux (x) uy) rho (same)^T   -- 4 separable 8-deep passes in smem.
// 512 threads/CTA: passes 1/2/4 are exactly one task per thread, short barrier
// chain, 16 warps/CTA for latency hiding. f32x2 packed math, float4 smem/gmem.

#define ST 132   // 128 + 4 pad: 16B-aligned rows, conflict-free row & col access
#define NT 512

typedef unsigned long long u64;

__device__ __forceinline__ u64 pk2(float a, float b) {
    u64 r; asm("mov.b64 %0,{%1,%2};" : "=l"(r) : "f"(a), "f"(b)); return r;
}
__device__ __forceinline__ u64 mul2(u64 a, u64 b) {
    u64 r; asm("mul.rn.f32x2 %0,%1,%2;" : "=l"(r) : "l"(a), "l"(b)); return r;
}
__device__ __forceinline__ void fma2(u64& d, u64 a, u64 b) {
    asm("fma.rn.f32x2 %0,%1,%2,%0;" : "+l"(d) : "l"(a), "l"(b));
}

extern __shared__ float smf[];

__global__ __launch_bounds__(NT, 2)
void qconv2d_kernel(const float* __restrict__ rho,
                    const float* __restrict__ ux,
                    const float* __restrict__ uy,
                    const float* __restrict__ uc,
                    float* __restrict__ out) {
    float* A    = smf;                         // 128*132 floats
    u64*   uxd  = (u64*)(smf + 128 * ST);      // 64: (ux[k,i], ux[k,i])
    u64*   uyd  = uxd + 64;                    // 64: (uy[k,j], uy[k,j])
    u64*   uypp = uyd + 64;                    // 32: (uy[2kp,j], uy[2kp+1,j])
    u64*   sccd = uypp + 32;                   // 8:  dup (uc[c,e+2])

    const int t = threadIdx.x;
    const int b = blockIdx.x;

    if (t < 64) { float vx = ux[t], vy = uy[t]; uxd[t] = pk2(vx, vx); uyd[t] = pk2(vy, vy); }
    else if (t < 96) {
        int m = t - 64, kp = m >> 3, j = m & 7;
        uypp[m] = pk2(uy[(2 * kp) * 8 + j], uy[(2 * kp + 1) * 8 + j]);
    } else if (t < 104) {
        int m = t - 96; float v = uc[(m >> 1) * 4 + 2 + (m & 1)];
        sccd[m] = pk2(v, v);
    }

    // ---- Load rho[b] (128x128): 8 front-batched LDG.128 (MLP 8) -> STS.128.
    {
        const float4* rb4 = (const float4*)(rho + (size_t)b * 16384);
        float4 v[8];
#pragma unroll
        for (int k = 0; k < 8; k++) v[k] = rb4[t + NT * k];
#pragma unroll
        for (int k = 0; k < 8; k++) {
            int idx = t + NT * k;
            *(float4*)&A[(idx >> 5) * ST + 4 * (idx & 31)] = v[k];
        }
    }
    __syncthreads();

    // ---- Pass 1 (rows, uy over j): rows gi*8+j -> gi*8+kj, one task/thread.
    {
        int s4 = t & 31, gi = t >> 5;            // gi = (e,i) 0..15
        ulonglong2 in[8];
#pragma unroll
        for (int j = 0; j < 8; j++) in[j] = *(ulonglong2*)&A[(gi * 8 + j) * ST + 4 * s4];
#pragma unroll
        for (int k = 0; k < 8; k++) {
            u64 c0 = uyd[k * 8];
            u64 ax = mul2(c0, in[0].x), ay = mul2(c0, in[0].y);
#pragma unroll
            for (int j = 1; j < 8; j++) { u64 c = uyd[k * 8 + j]; fma2(ax, c, in[j].x); fma2(ay, c, in[j].y); }
            ulonglong2 o; o.x = ax; o.y = ay;
            *(ulonglong2*)&A[(gi * 8 + k) * ST + 4 * s4] = o;
        }
    }
    __syncthreads();

    // ---- Pass 2 (rows, ux over i): rows e*64+i*8+kj -> e*64+k*8+kj.
    {
        int s4 = t & 31, rem = t >> 5;
        int kj = rem & 7, e = rem >> 3;
        ulonglong2 in[8];
#pragma unroll
        for (int i = 0; i < 8; i++) in[i] = *(ulonglong2*)&A[(e * 64 + i * 8 + kj) * ST + 4 * s4];
#pragma unroll
        for (int k = 0; k < 8; k++) {
            u64 c0 = uxd[k * 8];
            u64 ax = mul2(c0, in[0].x), ay = mul2(c0, in[0].y);
#pragma unroll
            for (int i = 1; i < 8; i++) { u64 c = uxd[k * 8 + i]; fma2(ax, c, in[i].x); fma2(ay, c, in[i].y); }
            ulonglong2 o; o.x = ax; o.y = ay;
            *(ulonglong2*)&A[(e * 64 + k * 8 + kj) * ST + 4 * s4] = o;
        }
    }
    __syncthreads();

    // ---- Pass 3 (cols, uy over j'): cols cg*8+j' -> cg*8+kj', paired outputs.
#pragma unroll 1
    for (int it = 0; it < 4; it++) {
        int task = t + NT * it;
        int r = task & 127, cg = task >> 7;      // cg = (e',i') 0..15
        float4 p = *(float4*)&A[r * ST + cg * 8];
        float4 q = *(float4*)&A[r * ST + cg * 8 + 4];
        u64 d0 = pk2(p.x, p.x), d1 = pk2(p.y, p.y), d2 = pk2(p.z, p.z), d3 = pk2(p.w, p.w);
        u64 d4 = pk2(q.x, q.x), d5 = pk2(q.y, q.y), d6 = pk2(q.z, q.z), d7 = pk2(q.w, q.w);
        u64 o[4];
#pragma unroll
        for (int kp = 0; kp < 4; kp++) {
            u64 acc = mul2(uypp[kp * 8 + 0], d0);
            fma2(acc, uypp[kp * 8 + 1], d1); fma2(acc, uypp[kp * 8 + 2], d2);
            fma2(acc, uypp[kp * 8 + 3], d3); fma2(acc, uypp[kp * 8 + 4], d4);
            fma2(acc, uypp[kp * 8 + 5], d5); fma2(acc, uypp[kp * 8 + 6], d6);
            fma2(acc, uypp[kp * 8 + 7], d7);
            o[kp] = acc;
        }
        ulonglong2 w0, w1; w0.x = o[0]; w0.y = o[1]; w1.x = o[2]; w1.y = o[3];
        *(ulonglong2*)&A[r * ST + cg * 8] = w0;
        *(ulonglong2*)&A[r * ST + cg * 8 + 4] = w1;
    }
    __syncthreads();

    // ---- Pass 4 (cols, ux over i'): cols e2*64+i*8+(4*kjq..+3), one task/thread.
    {
        int r = t & 127, e2 = (t >> 7) & 1, kjq = t >> 8;
        int base = r * ST + e2 * 64 + 4 * kjq;
        ulonglong2 in[8];
#pragma unroll
        for (int i = 0; i < 8; i++) in[i] = *(ulonglong2*)&A[base + 8 * i];
#pragma unroll
        for (int k = 0; k < 8; k++) {
            u64 c0 = uxd[k * 8];
            u64 ax = mul2(c0, in[0].x), ay = mul2(c0, in[0].y);
#pragma unroll
            for (int i = 1; i < 8; i++) { u64 c = uxd[k * 8 + i]; fma2(ax, c, in[i].x); fma2(ay, c, in[i].y); }
            ulonglong2 o; o.x = ax; o.y = ay;
            *(ulonglong2*)&A[base + 8 * k] = o;
        }
    }
    __syncthreads();

    // ---- Epilogue: channel expansion + STG.128.
    // t -> (q: col quad 0..15, cp: out col channel 0..3, rr: 8-row group 0..7).
    {
        const int q  = t & 15;
        const int cp = (t >> 4) & 3;
        const int rr = t >> 6;
        const u64 k0d = sccd[2 * cp], k1d = sccd[2 * cp + 1];
        const u64 s0 = sccd[0], s1 = sccd[1], s2 = sccd[2], s3 = sccd[3];
        const u64 s4 = sccd[4], s5 = sccd[5], s6 = sccd[6], s7 = sccd[7];
        float* ob = out + (size_t)b * 65536 + cp * 64 + 4 * q;
#pragma unroll 1
        for (int pp = 0; pp < 8; pp++) {
            int P = rr * 8 + pp;
            ulonglong2 a00 = *(ulonglong2*)&A[P * ST + 4 * q];
            ulonglong2 a01 = *(ulonglong2*)&A[P * ST + 64 + 4 * q];
            ulonglong2 a10 = *(ulonglong2*)&A[(64 + P) * ST + 4 * q];
            ulonglong2 a11 = *(ulonglong2*)&A[(64 + P) * ST + 64 + 4 * q];
            u64 v0x = mul2(k0d, a00.x); fma2(v0x, k1d, a01.x);
            u64 v0y = mul2(k0d, a00.y); fma2(v0y, k1d, a01.y);
            u64 v1x = mul2(k0d, a10.x); fma2(v1x, k1d, a11.x);
            u64 v1y = mul2(k0d, a10.y); fma2(v1y, k1d, a11.y);
            ulonglong2 w;
            w.x = mul2(s0, v0x); fma2(w.x, s1, v1x);
            w.y = mul2(s0, v0y); fma2(w.y, s1, v1y);
            *(ulonglong2*)&ob[(size_t)(0 * 64 + P) * 256] = w;
            w.x = mul2(s2, v0x); fma2(w.x, s3, v1x);
            w.y = mul2(s2, v0y); fma2(w.y, s3, v1y);
            *(ulonglong2*)&ob[(size_t)(1 * 64 + P) * 256] = w;
            w.x = mul2(s4, v0x); fma2(w.x, s5, v1x);
            w.y = mul2(s4, v0y); fma2(w.y, s5, v1y);
            *(ulonglong2*)&ob[(size_t)(2 * 64 + P) * 256] = w;
            w.x = mul2(s6, v0x); fma2(w.x, s7, v1x);
            w.y = mul2(s6, v0y); fma2(w.y, s7, v1y);
            *(ulonglong2*)&ob[(size_t)(3 * 64 + P) * 256] = w;
        }
    }
}

extern "C" void kernel_launch(void* const* d_in, const int* in_sizes, int n_in,
                              void* d_out, int out_size) {
    const float* rho = (const float*)d_in[0];   // [256,128,128]
    const float* ux  = (const float*)d_in[1];   // [8,8]
    const float* uy  = (const float*)d_in[2];   // [8,8]
    const float* uc  = (const float*)d_in[3];   // [4,4]
    float* out = (float*)d_out;                 // [256,256,256]

    const size_t smem = (128 * ST) * sizeof(float)
                      + (64 + 64 + 32 + 8) * sizeof(u64);   // 68928 B -> 2 CTAs/SM
    cudaFuncSetAttribute(qconv2d_kernel,
                         cudaFuncAttributeMaxDynamicSharedMemorySize, (int)smem);
    qconv2d_kernel<<<256, NT, smem>>>(rho, ux, uy, uc, out);
}

// round 6
// speedup vs baseline: 1.3045x; 1.0089x over previous
#include <cuda_runtime.h>
#include <cstdint>

// QConv2d fused: new_rho = U rho_big U^T, U = kron(uc, ux (x) uy).
//   new_rho[(c,P),(c',P')] = sum_{e,e'} cc[c,e] cc[c',e'] A[(e,P),(e',P')]
//   cc[c,e]=uc[c,e+2],  A = (I2 (x) ux (x) uy) rho (same)^T  (4 separable passes).
// Epilogue stages 16-P-row chunks (all 4 c-blocks, 64 KB) in smem and streams
// them with cp.async.bulk (TMA path), double-buffered. 4 chunks cover P=0..63.
// Pass 1 reads rho straight from GMEM (coalesced LDG.128), no initial STS.

#define ST 132   // A row stride: 128 + 4 pad, 16B-aligned, conflict-free
#define NT 512

typedef unsigned long long u64;

__device__ __forceinline__ u64 pk2(float a, float b) {
    u64 r; asm("mov.b64 %0,{%1,%2};" : "=l"(r) : "f"(a), "f"(b)); return r;
}
__device__ __forceinline__ u64 mul2(u64 a, u64 b) {
    u64 r; asm("mul.rn.f32x2 %0,%1,%2;" : "=l"(r) : "l"(a), "l"(b)); return r;
}
__device__ __forceinline__ void fma2(u64& d, u64 a, u64 b) {
    asm("fma.rn.f32x2 %0,%1,%2,%0;" : "+l"(d) : "l"(a), "l"(b));
}
__device__ __forceinline__ uint32_t s2u32(const void* p) {
    uint32_t a;
    asm("{ .reg .u64 t; cvta.to.shared.u64 t, %1; cvt.u32.u64 %0, t; }" : "=r"(a) : "l"(p));
    return a;
}

extern __shared__ float smf[];

__global__ __launch_bounds__(NT, 1)
void qconv2d_kernel(const float* __restrict__ rho,
                    const float* __restrict__ ux,
                    const float* __restrict__ uy,
                    const float* __restrict__ uc,
                    float* __restrict__ out) {
    float* A     = smf;                          // 128*132 = 16896 floats
    float* stage = smf + 128 * ST;               // 2 x 16384 floats (2 x 64 KB)
    u64*   uxd   = (u64*)(stage + 32768);        // 64
    u64*   uyd   = uxd + 64;                     // 64
    u64*   uypp  = uyd + 64;                     // 32
    u64*   sccd  = uypp + 32;                    // 8

    const int t = threadIdx.x;
    const int b = blockIdx.x;

    if (t < 64) { float vx = ux[t], vy = uy[t]; uxd[t] = pk2(vx, vx); uyd[t] = pk2(vy, vy); }
    else if (t < 96) {
        int m = t - 64, kp = m >> 3, j = m & 7;
        uypp[m] = pk2(uy[(2 * kp) * 8 + j], uy[(2 * kp + 1) * 8 + j]);
    } else if (t < 104) {
        int m = t - 96; float v = uc[(m >> 1) * 4 + 2 + (m & 1)];
        sccd[m] = pk2(v, v);
    }

    // ---- Pass 1 (rows, uy over j), input straight from GMEM (coalesced).
    {
        int s4 = t & 31, gi = t >> 5;            // gi = (e,i) 0..15
        const float* rb = rho + (size_t)b * 16384 + 4 * s4;
        ulonglong2 in[8];
#pragma unroll
        for (int j = 0; j < 8; j++)
            in[j] = *(const ulonglong2*)(rb + (size_t)(gi * 8 + j) * 128);
        __syncthreads();                         // tables ready
#pragma unroll
        for (int k = 0; k < 8; k++) {
            u64 c0 = uyd[k * 8];
            u64 ax = mul2(c0, in[0].x), ay = mul2(c0, in[0].y);
#pragma unroll
            for (int j = 1; j < 8; j++) { u64 c = uyd[k * 8 + j]; fma2(ax, c, in[j].x); fma2(ay, c, in[j].y); }
            ulonglong2 o; o.x = ax; o.y = ay;
            *(ulonglong2*)&A[(gi * 8 + k) * ST + 4 * s4] = o;
        }
    }
    __syncthreads();

    // ---- Pass 2 (rows, ux over i): rows e*64+i*8+kj -> e*64+k*8+kj.
    {
        int s4 = t & 31, rem = t >> 5;
        int kj = rem & 7, e = rem >> 3;
        ulonglong2 in[8];
#pragma unroll
        for (int i = 0; i < 8; i++) in[i] = *(ulonglong2*)&A[(e * 64 + i * 8 + kj) * ST + 4 * s4];
#pragma unroll
        for (int k = 0; k < 8; k++) {
            u64 c0 = uxd[k * 8];
            u64 ax = mul2(c0, in[0].x), ay = mul2(c0, in[0].y);
#pragma unroll
            for (int i = 1; i < 8; i++) { u64 c = uxd[k * 8 + i]; fma2(ax, c, in[i].x); fma2(ay, c, in[i].y); }
            ulonglong2 o; o.x = ax; o.y = ay;
            *(ulonglong2*)&A[(e * 64 + k * 8 + kj) * ST + 4 * s4] = o;
        }
    }
    __syncthreads();

    // ---- Pass 3 (cols, uy over j'): cols cg*8+j' -> cg*8+kj', paired outputs.
#pragma unroll 1
    for (int it = 0; it < 4; it++) {
        int task = t + NT * it;
        int r = task & 127, cg = task >> 7;      // cg = (e',i') 0..15
        float4 p = *(float4*)&A[r * ST + cg * 8];
        float4 q = *(float4*)&A[r * ST + cg * 8 + 4];
        u64 d0 = pk2(p.x, p.x), d1 = pk2(p.y, p.y), d2 = pk2(p.z, p.z), d3 = pk2(p.w, p.w);
        u64 d4 = pk2(q.x, q.x), d5 = pk2(q.y, q.y), d6 = pk2(q.z, q.z), d7 = pk2(q.w, q.w);
        u64 o[4];
#pragma unroll
        for (int kp = 0; kp < 4; kp++) {
            u64 acc = mul2(uypp[kp * 8 + 0], d0);
            fma2(acc, uypp[kp * 8 + 1], d1); fma2(acc, uypp[kp * 8 + 2], d2);
            fma2(acc, uypp[kp * 8 + 3], d3); fma2(acc, uypp[kp * 8 + 4], d4);
            fma2(acc, uypp[kp * 8 + 5], d5); fma2(acc, uypp[kp * 8 + 6], d6);
            fma2(acc, uypp[kp * 8 + 7], d7);
            o[kp] = acc;
        }
        ulonglong2 w0, w1; w0.x = o[0]; w0.y = o[1]; w1.x = o[2]; w1.y = o[3];
        *(ulonglong2*)&A[r * ST + cg * 8] = w0;
        *(ulonglong2*)&A[r * ST + cg * 8 + 4] = w1;
    }
    __syncthreads();

    // ---- Pass 4 (cols, ux over i'): cols e2*64+i*8+(4*kjq..+3), one task/thread.
    {
        int r = t & 127, e2 = (t >> 7) & 1, kjq = t >> 8;
        int base = r * ST + e2 * 64 + 4 * kjq;
        ulonglong2 in[8];
#pragma unroll
        for (int i = 0; i < 8; i++) in[i] = *(ulonglong2*)&A[base + 8 * i];
#pragma unroll
        for (int k = 0; k < 8; k++) {
            u64 c0 = uxd[k * 8];
            u64 ax = mul2(c0, in[0].x), ay = mul2(c0, in[0].y);
#pragma unroll
            for (int i = 1; i < 8; i++) { u64 c = uxd[k * 8 + i]; fma2(ax, c, in[i].x); fma2(ay, c, in[i].y); }
            ulonglong2 o; o.x = ax; o.y = ay;
            *(ulonglong2*)&A[base + 8 * k] = o;
        }
    }

    // ---- Epilogue: channel expansion into smem staging + bulk async stores.
    // Chunk n (n=0..3): P rows n*16 .. n*16+15 (P in 0..63), all 4 c-blocks.
    // Output rows covered: c*64 + P for c=0..3 -> 64 rows/chunk, 256 total.
    const int q  = t & 15;
    const int cp = (t >> 4) & 3;
    const int pr = t >> 6;                        // 0..7
    const u64 k0d = sccd[2 * cp], k1d = sccd[2 * cp + 1];
    const u64 s0 = sccd[0], s1 = sccd[1], s2 = sccd[2], s3 = sccd[3];
    const u64 s4 = sccd[4], s5 = sccd[5], s6 = sccd[6], s7 = sccd[7];
    float* ob = out + (size_t)b * 65536;

#pragma unroll 1
    for (int n = 0; n < 4; n++) {
        float* Sb = stage + (n & 1) * 16384;
        if (t == 0 && n >= 2)
            asm volatile("cp.async.bulk.wait_group.read 1;" ::: "memory");
        __syncthreads();                          // buffer free (and pass-4 done, n=0)
#pragma unroll
        for (int h = 0; h < 2; h++) {
            int P  = n * 16 + h * 8 + pr;         // 0..63
            int pl = h * 8 + pr;                  // local row in chunk 0..15
            ulonglong2 a00 = *(ulonglong2*)&A[P * ST + 4 * q];
            ulonglong2 a01 = *(ulonglong2*)&A[P * ST + 64 + 4 * q];
            ulonglong2 a10 = *(ulonglong2*)&A[(64 + P) * ST + 4 * q];
            ulonglong2 a11 = *(ulonglong2*)&A[(64 + P) * ST + 64 + 4 * q];
            u64 v0x = mul2(k0d, a00.x); fma2(v0x, k1d, a01.x);
            u64 v0y = mul2(k0d, a00.y); fma2(v0y, k1d, a01.y);
            u64 v1x = mul2(k0d, a10.x); fma2(v1x, k1d, a11.x);
            u64 v1y = mul2(k0d, a10.y); fma2(v1y, k1d, a11.y);
            float* sp = Sb + pl * 256 + cp * 64 + 4 * q;
            ulonglong2 w;
            w.x = mul2(s0, v0x); fma2(w.x, s1, v1x);
            w.y = mul2(s0, v0y); fma2(w.y, s1, v1y);
            *(ulonglong2*)(sp + 0 * 4096) = w;    // c=0 block
            w.x = mul2(s2, v0x); fma2(w.x, s3, v1x);
            w.y = mul2(s2, v0y); fma2(w.y, s3, v1y);
            *(ulonglong2*)(sp + 1 * 4096) = w;    // c=1 block
            w.x = mul2(s4, v0x); fma2(w.x, s5, v1x);
            w.y = mul2(s4, v0y); fma2(w.y, s5, v1y);
            *(ulonglong2*)(sp + 2 * 4096) = w;    // c=2 block
            w.x = mul2(s6, v0x); fma2(w.x, s7, v1x);
            w.y = mul2(s6, v0y); fma2(w.y, s7, v1y);
            *(ulonglong2*)(sp + 3 * 4096) = w;    // c=3 block
        }
        __syncthreads();                          // chunk staged
        if (t == 0) {
            asm volatile("fence.proxy.async.shared::cta;" ::: "memory");
            uint32_t src = s2u32(Sb);
#pragma unroll
            for (int c = 0; c < 4; c++) {
                float* dst = ob + (size_t)(c * 64 + n * 16) * 256;   // row <= 240
                asm volatile("cp.async.bulk.global.shared::cta.bulk_group [%0], [%1], %2;"
                             :: "l"(dst), "r"(src + c * 16384u), "n"(16384) : "memory");
            }
            asm volatile("cp.async.bulk.commit_group;" ::: "memory");
        }
    }
    if (t == 0)
        asm volatile("cp.async.bulk.wait_group 0;" ::: "memory");
}

extern "C" void kernel_launch(void* const* d_in, const int* in_sizes, int n_in,
                              void* d_out, int out_size) {
    const float* rho = (const float*)d_in[0];   // [256,128,128]
    const float* ux  = (const float*)d_in[1];   // [8,8]
    const float* uy  = (const float*)d_in[2];   // [8,8]
    const float* uc  = (const float*)d_in[3];   // [4,4]
    float* out = (float*)d_out;                 // [256,256,256]

    const size_t smem = (128 * ST + 32768) * sizeof(float)
                      + (64 + 64 + 32 + 8) * sizeof(u64);   // 200,000 B -> 1 CTA/SM
    cudaFuncSetAttribute(qconv2d_kernel,
                         cudaFuncAttributeMaxDynamicSharedMemorySize, (int)smem);
    qconv2d_kernel<<<256, NT, smem>>>(rho, ux, uy, uc, out);
}